// round 8
// baseline (speedup 1.0000x reference)
#include <cuda_runtime.h>
#include <math.h>

#define HDIM 512
#define TILE_R 16
#define SEG_L 512          // output days per scan block
#define WARM 1024          // warmup days (contraction burn-in)
#define SK 512             // S-convolution taps

// ------------------------- scratch (static device globals; no allocs) ------
__device__ float  g_H1[50000 * HDIM];   // reused: H1 for parnet, G1 for resnet
__device__ float  g_P[3200 * 27];       // per-block constrained-param partial sums
__device__ float  g_pm[64];             // 27 physical params + derived constants
__device__ float4 g_dayA[50176];        // {GM, TRG, fD, EV}
__device__ float4 g_dayB[50176];        // {I, R, cap, meltpot}
__device__ __align__(16) float g_dayC[50176];  // cold flag

__constant__ float c_SCALES[27] = {400,1,1,1,1,12,10,10,1,1,1,1,1,10,1,1,1,5,1,1,4,1,1,180,1,1,10};

// ------------------------- parameter constraint ----------------------------
__device__ __forceinline__ float clampf(float v, float lo, float hi) {
    return fminf(fmaxf(v, lo), hi);
}
__device__ __forceinline__ float constrain(float v, int j) {
    switch (j) {
        case 0:  return clampf(v, 0.f, 2.f);
        case 1: case 2: case 20: case 21: case 23: case 24: case 25: case 26:
                 return fmaxf(v, 0.f);
        case 4:  return clampf(v, 0.f, 2.5f);
        case 5:  return clampf(v, 0.01f, 3.f);
        case 6:  return clampf(v, -0.2f, 2.1f);
        case 7:  return clampf(v, 0.23f, 3.0f);
        case 8:  return clampf(v, -1.f, 0.f);
        case 9:  return clampf(v, 0.f, 0.7f);
        case 10: case 16: return 1.f / (1.f + expf(-v));
        case 13: return clampf(v, 0.f, 1.0f);
        case 14: return clampf(v, 0.f, 1.2f);
        case 15: return clampf(v, 0.f, 2.5f);
        case 17: return clampf(v, 0.f, 1.f);
        case 19: return clampf(v, 0.f, 1.f / 0.75f);
        default: return v;   // 3, 11, 12, 18, 22
    }
}

// ------------------------- first linear + ELU ------------------------------
template<int IN>
__global__ void k_lin1(const float* __restrict__ X, const float* __restrict__ W,
                       const float* __restrict__ b, int T) {
    int idx = blockIdx.x * blockDim.x + threadIdx.x;
    if (idx >= T * HDIM) return;
    int t = idx >> 9, j = idx & 511;
    float s = b[j];
    const float* xr = X + t * IN;
    #pragma unroll
    for (int i = 0; i < IN; i++) s = fmaf(xr[i], W[i * HDIM + j], s);
    g_H1[idx] = s > 0.f ? s : expm1f(s);
}

// ------------------------- mid GEMM (H@W1+b1) fused with final layer -------
// Stage 1 uses packed fma.rn.f32x2 (FFMA2): rows paired in the f32x2 lanes.
// SMEM buffer is viewed transposed+padded [HDIM][18] during stage 1, then
// reused as [TILE_R][HDIM] for the stage-2 input tile.
template<int NOUT, bool CONS>
__global__ void k_mid(const float* __restrict__ W1, const float* __restrict__ b1,
                      const float* __restrict__ W2, const float* __restrict__ b2,
                      float* __restrict__ out, int T) {
    __shared__ float sBuf[HDIM * 18];      // 36 KB, dual-view
    __shared__ float sP[TILE_R][32];
    int tid = threadIdx.x;
    int row0 = blockIdx.x * TILE_R;

    // stage H tile transposed: sBuf[c*18 + r]
    for (int i = tid; i < TILE_R * HDIM; i += 256) {
        int r = i >> 9, c = i & 511;
        int gr = row0 + r;
        sBuf[c * 18 + r] = (gr < T) ? g_H1[gr * HDIM + c] : 0.f;
    }
    __syncthreads();

    int c0 = tid * 2;
    unsigned long long acc0[8], acc1[8];   // 8 row-pairs x 2 cols
    #pragma unroll
    for (int p = 0; p < 8; p++) { acc0[p] = 0ull; acc1[p] = 0ull; }

    const unsigned long long* Wp = reinterpret_cast<const unsigned long long*>(W1);
    #pragma unroll 2
    for (int k = 0; k < HDIM; k++) {
        unsigned long long wp = Wp[k * 256 + tid];      // (W1[k][c0], W1[k][c0+1])
        unsigned int wx, wy;
        asm("mov.b64 {%0,%1}, %2;" : "=r"(wx), "=r"(wy) : "l"(wp));
        unsigned long long w2a, w2b;
        asm("mov.b64 %0, {%1,%1};" : "=l"(w2a) : "r"(wx));
        asm("mov.b64 %0, {%1,%1};" : "=l"(w2b) : "r"(wy));
        const unsigned long long* hrow =
            reinterpret_cast<const unsigned long long*>(&sBuf[k * 18]);
        #pragma unroll
        for (int p = 0; p < 8; p++) {
            unsigned long long h2 = hrow[p];            // (h[2p][k], h[2p+1][k])
            asm("fma.rn.f32x2 %0, %1, %2, %0;" : "+l"(acc0[p]) : "l"(h2), "l"(w2a));
            asm("fma.rn.f32x2 %0, %1, %2, %0;" : "+l"(acc1[p]) : "l"(h2), "l"(w2b));
        }
    }
    float bb0 = b1[c0], bb1 = b1[c0 + 1];
    __syncthreads();   // everyone done reading sBuf (transposed view)

    // write stage-1 output into sBuf viewed as [TILE_R][HDIM] (float2 stores)
    #pragma unroll
    for (int p = 0; p < 8; p++) {
        unsigned int lo, hi;
        asm("mov.b64 {%0,%1}, %2;" : "=r"(lo), "=r"(hi) : "l"(acc0[p]));
        float a0lo = __uint_as_float(lo) + bb0, a0hi = __uint_as_float(hi) + bb0;
        asm("mov.b64 {%0,%1}, %2;" : "=r"(lo), "=r"(hi) : "l"(acc1[p]));
        float a1lo = __uint_as_float(lo) + bb1, a1hi = __uint_as_float(hi) + bb1;
        *reinterpret_cast<float2*>(&sBuf[(2 * p) * HDIM + c0])     = make_float2(a0lo, a1lo);
        *reinterpret_cast<float2*>(&sBuf[(2 * p + 1) * HDIM + c0]) = make_float2(a0hi, a1hi);
    }
    __syncthreads();

    for (int i = tid; i < TILE_R * NOUT; i += 256) {
        int r = i / NOUT, j = i - r * NOUT;
        float s = b2[j];
        for (int k = 0; k < HDIM; k++) s = fmaf(sBuf[r * HDIM + k], W2[k * NOUT + j], s);
        if (CONS) {
            sP[r][j] = (row0 + r < T) ? constrain(s, j) : 0.f;
        } else {
            if (row0 + r < T) out[(row0 + r) * NOUT + j] = s;
        }
    }
    if (CONS) {
        __syncthreads();
        if (tid < NOUT) {
            float s = 0.f;
            #pragma unroll
            for (int r = 0; r < TILE_R; r++) s += sP[r][tid];
            g_P[blockIdx.x * NOUT + tid] = s;
        }
    }
}

// ------------------------- reduce partials -> pm, derived constants --------
__global__ void k_reduce(int nblk, int T) {
    int j = threadIdx.x >> 5, lane = threadIdx.x & 31;
    if (j < 27) {
        float s = 0.f;
        for (int b = lane; b < nblk; b += 32) s += g_P[b * 27 + j];
        #pragma unroll
        for (int o = 16; o; o >>= 1) s += __shfl_down_sync(0xffffffffu, s, o);
        if (lane == 0) g_pm[j] = s / (float)T * c_SCALES[j];
    }
    __syncthreads();
    if (threadIdx.x == 0) {
        float sd = g_pm[0], fc = g_pm[1], pwp = g_pm[2], tauD = g_pm[3], tau = g_pm[5];
        g_pm[27] = fc * sd;                              // fcap
        g_pm[28] = 1.f / sd;                             // inv soildepth
        g_pm[29] = 1.f / (fc - pwp);                     // inv (FC - PWP)
        g_pm[30] = 1.f / g_pm[10];                       // inv soilthres
        g_pm[31] = 1.f / g_pm[16];                       // inv ETsoilthres
        g_pm[32] = 1.f - 1.f / tau;                      // a (S recurrence)
        g_pm[33] = 1.f / tau;
        g_pm[34] = 1.f / g_pm[7];                        // inv Smax
        float invTauD = (tauD > 0.f) ? 1.f / tauD : 0.f;
        g_pm[35] = invTauD;
        g_pm[36] = 1.f - invTauD;                        // c1: theta=min(st0, st0*c1+c2)
        g_pm[37] = (g_pm[20] <= 1e-8f) ? 1.f : 0.f;      // small CWmax
        g_pm[38] = g_pm[19] / 0.75f;                     // I0/0.75
        g_pm[39] = g_pm[27] * invTauD;                   // c2
    }
}

// ------------------------- day precompute + S via truncated convolution ----
__global__ void k_day(const float* __restrict__ cin, int T) {
    __shared__ float sx[SK + 256 - 1 + 1];   // tair[base-(SK-1) .. base+255]
    __shared__ float pw[SK + 1];
    int base = blockIdx.x * 256;
    int tid = threadIdx.x;

    float tau = g_pm[5];
    float a = 1.f - 1.f / tau, invtau = 1.f / tau;
    float S0 = g_pm[6], invSmax = g_pm[34], Sinit = g_pm[26];

    for (int i = tid; i < SK + 255; i += 256) {
        int g = base - (SK - 1) + i;
        sx[i] = (g >= 0 && g < T) ? cin[g * 7 + 1] : 0.f;
    }
    for (int j = tid; j <= SK; j += 256) pw[j] = __powf(a, (float)j);
    __syncthreads();

    int t = base + tid;
    if (t >= T) return;

    int Kt = min(t + 1, SK);
    int off = tid + (SK - 1);    // sx index of x_t
    float s0 = 0.f, s1 = 0.f, s2 = 0.f, s3 = 0.f;
    int j = 0;
    for (; j + 4 <= Kt; j += 4) {
        s0 = fmaf(pw[j + 0], sx[off - j - 0], s0);
        s1 = fmaf(pw[j + 1], sx[off - j - 1], s1);
        s2 = fmaf(pw[j + 2], sx[off - j - 2], s2);
        s3 = fmaf(pw[j + 3], sx[off - j - 3], s3);
    }
    for (; j < Kt; j++) s0 = fmaf(pw[j], sx[off - j], s0);
    float S = ((s0 + s1) + (s2 + s3)) * invtau;
    if (t < SK) S = fmaf(pw[t + 1], Sinit, S);
    float fS = fminf(fmaxf(S - S0, 0.f) * invSmax, 1.f);

    float beta = g_pm[4], kappa = g_pm[8], gamma = g_pm[9];
    float bCO2 = g_pm[11], xCO2 = g_pm[12];
    float ETbeta = g_pm[13], ETkappa = g_pm[14], ETchi = g_pm[15];
    float MeltCoef = g_pm[18], CWmax = g_pm[20], ST = g_pm[21], T0p = g_pm[22];
    float Icoef = g_pm[38];

    float precip = cin[t * 7 + 0], tair = cin[t * 7 + 1], par = cin[t * 7 + 2];
    float vpd = cin[t * 7 + 3], fapar = cin[t * 7 + 4], co2 = cin[t * 7 + 6];

    float fD = fminf(__expf(kappa * vpd), 1.f);
    float fL = __fdividef(1.f, fmaf(gamma, par, 1.f));
    float G = beta * par * fapar * fS * fL;
    float lc = __logf(co2 * (1.f / 380.f));
    float GM = G * fmaf(bCO2, lc, 1.f);
    float fCO2et = fmaf(xCO2, lc, 1.f);
    float TRG = vpd * ETbeta * G * __powf(vpd, -ETkappa) * fCO2et;
    float EV = ETchi * (1.f - fapar) * par;
    float I = (tair > ST) ? precip * fapar * Icoef : 0.f;
    float R = precip - I;
    float cap = CWmax * fapar;
    float meltpot = (tair >= T0p) ? MeltCoef * (tair - T0p) : 0.f;

    g_dayA[t] = make_float4(GM, TRG, fD, EV);
    g_dayB[t] = make_float4(I, R, cap, meltpot);
    g_dayC[t] = (tair < ST) ? 1.f : 0.f;
}

// ------------------------- block-parallel decoupled water scan -------------
__global__ void k_scanP(const float* __restrict__ sw, float* __restrict__ pp, int T) {
    if (threadIdx.x != 0) return;
    int start = blockIdx.x * SEG_L;
    if (start >= T) return;
    int end = min(start + SEG_L, T);
    int wstart = max(start - WARM, 0);

    float PWP = g_pm[2], soilthres = g_pm[10], ETst = g_pm[16], ETnu = g_pm[17];
    float invSD = g_pm[28], invRange = g_pm[29], invST = g_pm[30], invETst = g_pm[31];
    float c1 = g_pm[36], c2 = g_pm[39];
    bool smallcw = g_pm[37] > 0.5f;
    float a1 = invSD * invRange, b1 = -PWP * invRange;   // REW = theta*a1 + b1

    float theta = g_pm[23], canw = g_pm[24], snow = g_pm[25];
    float sw0 = sw[0], invsw1 = 1.f / sw[1];

    auto step = [&](const float4 da, const float4 db, float cold,
                    float& gpp, float& et) {
        float REW = fmaf(theta, a1, b1);
        float fWmid = REW * invST;
        float pwin = fmaxf(fminf(fWmid, 1.f), 1e-12f);
        float pw = __powf(pwin, ETnu);
        float fW = (REW < soilthres) ? ((REW > 0.01f) ? fWmid : 0.f) : 1.f;
        float fE = fminf(da.z, fW);
        gpp = da.x * fE;
        float transp = da.y * fE * pw;

        float fwm2 = REW * invETst;
        float fWet = (REW < ETst) ? ((REW > 0.01f) ? fwm2 : 0.f) : 1.f;

        float I = db.x, R = db.y, cap = db.z;
        bool over = (I + canw) > cap;
        float tf = smallcw ? (R + I) : (over ? (R + I + canw - cap) : R);
        float canw1 = smallcw ? canw : (over ? cap : canw + I);
        if (canw1 > 1e-8f) fWet = 1.f;
        float evap = da.w * fWet;

        float newsnow = cold * tf;
        tf = tf - newsnow;
        float snn = snow + newsnow;
        float melt = fminf(db.w, snn);
        float snow1 = snn - melt;

        et = transp + evap;
        float etsoil = fmaxf(et - (canw1 + snow1), 0.f);
        float st0 = fmaxf(theta + tf + melt - etsoil, 1e-4f);
        theta = fminf(st0, fmaf(st0, c1, c2));

        canw = fmaxf(canw1 - et, 0.f);
        float rem = fmaxf(et - canw1, 0.f);
        snow = fmaxf(snow1 - rem, 0.f);
    };

    int t = wstart;
    for (; t + 4 <= start; t += 4) {
        float4 a0 = g_dayA[t], a01 = g_dayA[t + 1], a2 = g_dayA[t + 2], a3 = g_dayA[t + 3];
        float4 b0 = g_dayB[t], b01 = g_dayB[t + 1], b2 = g_dayB[t + 2], b3 = g_dayB[t + 3];
        float4 cc = *reinterpret_cast<const float4*>(&g_dayC[t]);
        float g, e;
        step(a0, b0, cc.x, g, e);
        step(a01, b01, cc.y, g, e);
        step(a2, b2, cc.z, g, e);
        step(a3, b3, cc.w, g, e);
    }
    for (; t < start; t++) { float g, e; step(g_dayA[t], g_dayB[t], g_dayC[t], g, e); }
    for (; t + 4 <= end; t += 4) {
        float4 a0 = g_dayA[t], a01 = g_dayA[t + 1], a2 = g_dayA[t + 2], a3 = g_dayA[t + 3];
        float4 b0 = g_dayB[t], b01 = g_dayB[t + 1], b2 = g_dayB[t + 2], b3 = g_dayB[t + 3];
        float4 cc = *reinterpret_cast<const float4*>(&g_dayC[t]);
        float g, e;
        step(a0, b0, cc.x, g, e);
        pp[3 * t + 0] = g; pp[3 * t + 1] = e; pp[3 * t + 2] = (theta - sw0) * invsw1;
        step(a01, b01, cc.y, g, e);
        pp[3 * t + 3] = g; pp[3 * t + 4] = e; pp[3 * t + 5] = (theta - sw0) * invsw1;
        step(a2, b2, cc.z, g, e);
        pp[3 * t + 6] = g; pp[3 * t + 7] = e; pp[3 * t + 8] = (theta - sw0) * invsw1;
        step(a3, b3, cc.w, g, e);
        pp[3 * t + 9] = g; pp[3 * t + 10] = e; pp[3 * t + 11] = (theta - sw0) * invsw1;
    }
    for (; t < end; t++) {
        float g, e;
        step(g_dayA[t], g_dayB[t], g_dayC[t], g, e);
        pp[3 * t + 0] = g; pp[3 * t + 1] = e; pp[3 * t + 2] = (theta - sw0) * invsw1;
    }
}

// ------------------------- launcher ----------------------------------------
extern "C" void kernel_launch(void* const* d_in, const int* in_sizes, int n_in,
                              void* d_out, int out_size) {
    const float* x   = (const float*)d_in[0];
    const float* cin = (const float*)d_in[1];
    const float* sw  = (const float*)d_in[2];
    // d_in[3] = tp (unused)
    const float* pW0 = (const float*)d_in[4];
    const float* pb0 = (const float*)d_in[5];
    const float* pW1 = (const float*)d_in[6];
    const float* pb1 = (const float*)d_in[7];
    const float* pW2 = (const float*)d_in[8];
    const float* pb2 = (const float*)d_in[9];
    const float* rW0 = (const float*)d_in[10];
    const float* rb0 = (const float*)d_in[11];
    const float* rW1 = (const float*)d_in[12];
    const float* rb1 = (const float*)d_in[13];
    const float* rW2 = (const float*)d_in[14];
    const float* rb2 = (const float*)d_in[15];

    int T = in_sizes[0] / 12;
    float* yhat = (float*)d_out;           // [T, 2]
    float* pp = yhat + 2 * T;              // [T, 3]

    int blkA = (T * HDIM + 255) / 256;
    int nblk = (T + TILE_R - 1) / TILE_R;
    int nseg = (T + SEG_L - 1) / SEG_L;

    // parnet
    k_lin1<12><<<blkA, 256>>>(x, pW0, pb0, T);
    k_mid<27, true><<<nblk, 256>>>(pW1, pb1, pW2, pb2, nullptr, T);
    k_reduce<<<1, 27 * 32>>>(nblk, T);

    // PRELES
    k_day<<<(T + 255) / 256, 256>>>(cin, T);
    k_scanP<<<nseg, 32>>>(sw, pp, T);

    // resnet
    k_lin1<3><<<blkA, 256>>>(pp, rW0, rb0, T);
    k_mid<2, false><<<nblk, 256>>>(rW1, rb1, rW2, rb2, yhat, T);
}

// round 9
// speedup vs baseline: 2.8046x; 2.8046x over previous
#include <cuda_runtime.h>
#include <math.h>

#define HDIM 512
#define TILE_R 16
#define SEG_L 512          // output days per scan block
#define WARM 1024          // warmup days (contraction burn-in)
#define SK 512             // S-convolution taps

// ------------------------- scratch (static device globals; no allocs) ------
__device__ float  g_P[3200 * 27];       // per-block constrained-param partial sums
__device__ float  g_pm[64];             // 27 physical params + derived constants
__device__ float  g_W12p[HDIM * 27];    // folded parnet W1@W2
__device__ float  g_b12p[32];           // folded parnet bias
__device__ float  g_W12r[HDIM * 2];     // folded resnet rW1@rW2
__device__ float  g_b12r[4];            // folded resnet bias
__device__ float4 g_dayA[50176];        // {GM, TRG, fD, EV}
__device__ float4 g_dayB[50176];        // {I, R, cap, meltpot}
__device__ __align__(16) float g_dayC[50176];  // cold flag

__constant__ float c_SCALES[27] = {400,1,1,1,1,12,10,10,1,1,1,1,1,10,1,1,1,5,1,1,4,1,1,180,1,1,10};

// ------------------------- parameter constraint ----------------------------
__device__ __forceinline__ float clampf(float v, float lo, float hi) {
    return fminf(fmaxf(v, lo), hi);
}
__device__ __forceinline__ float constrain(float v, int j) {
    switch (j) {
        case 0:  return clampf(v, 0.f, 2.f);
        case 1: case 2: case 20: case 21: case 23: case 24: case 25: case 26:
                 return fmaxf(v, 0.f);
        case 4:  return clampf(v, 0.f, 2.5f);
        case 5:  return clampf(v, 0.01f, 3.f);
        case 6:  return clampf(v, -0.2f, 2.1f);
        case 7:  return clampf(v, 0.23f, 3.0f);
        case 8:  return clampf(v, -1.f, 0.f);
        case 9:  return clampf(v, 0.f, 0.7f);
        case 10: case 16: return 1.f / (1.f + expf(-v));
        case 13: return clampf(v, 0.f, 1.0f);
        case 14: return clampf(v, 0.f, 1.2f);
        case 15: return clampf(v, 0.f, 2.5f);
        case 17: return clampf(v, 0.f, 1.f);
        case 19: return clampf(v, 0.f, 1.f / 0.75f);
        default: return v;   // 3, 11, 12, 18, 22
    }
}

// ------------------------- fold parnet W1@W2, b1@W2+b2 ---------------------
// 32 blocks x 256 threads; block handles 16 k-rows of W1 (staged in SMEM).
__global__ void k_fold(const float* __restrict__ W1, const float* __restrict__ b1,
                       const float* __restrict__ W2, const float* __restrict__ b2) {
    __shared__ float sW1[16 * HDIM];       // 32 KB
    __shared__ float sb[27][8];
    int tid = threadIdx.x;
    int k0 = blockIdx.x * 16;
    for (int i = tid; i < 16 * HDIM; i += 256)
        sW1[i] = W1[(k0 + (i >> 9)) * HDIM + (i & 511)];
    if (blockIdx.x == 0) {
        for (int i = tid; i < 27 * 8; i += 256) {
            int j = i >> 3, l = i & 7;
            float s = 0.f;
            for (int k = l * 64; k < l * 64 + 64; k++)
                s = fmaf(b1[k], W2[k * 27 + j], s);
            sb[j][l] = s;
        }
    }
    __syncthreads();
    for (int i = tid; i < 16 * 27; i += 256) {
        int kr = i / 27, j = i - kr * 27;
        float s = 0.f;
        const float* w1r = &sW1[kr * HDIM];
        #pragma unroll 4
        for (int m = 0; m < HDIM; m++)
            s = fmaf(w1r[m], W2[m * 27 + j], s);
        g_W12p[(k0 + kr) * 27 + j] = s;
    }
    if (blockIdx.x == 0 && tid < 27) {
        float s = b2[tid];
        #pragma unroll
        for (int l = 0; l < 8; l++) s += sb[tid][l];
        g_b12p[tid] = s;
    }
}

// ------------------------- fold resnet rW1@rW2, rb1@rW2+rb2 ----------------
__global__ void k_rfold(const float* __restrict__ W1, const float* __restrict__ b1,
                        const float* __restrict__ W2, const float* __restrict__ b2) {
    __shared__ float sW1[16 * HDIM];
    __shared__ float sb[2][8];
    int tid = threadIdx.x;
    int k0 = blockIdx.x * 16;
    for (int i = tid; i < 16 * HDIM; i += 256)
        sW1[i] = W1[(k0 + (i >> 9)) * HDIM + (i & 511)];
    if (blockIdx.x == 0) {
        for (int i = tid; i < 2 * 8; i += 256) {
            int j = i >> 3, l = i & 7;
            float s = 0.f;
            for (int k = l * 64; k < l * 64 + 64; k++)
                s = fmaf(b1[k], W2[k * 2 + j], s);
            sb[j][l] = s;
        }
    }
    __syncthreads();
    for (int i = tid; i < 16 * 2; i += 256) {
        int kr = i >> 1, j = i & 1;
        float s = 0.f;
        const float* w1r = &sW1[kr * HDIM];
        #pragma unroll 4
        for (int m = 0; m < HDIM; m++)
            s = fmaf(w1r[m], W2[m * 2 + j], s);
        g_W12r[(k0 + kr) * 2 + j] = s;
    }
    if (blockIdx.x == 0 && tid < 2) {
        float s = b2[tid];
        #pragma unroll
        for (int l = 0; l < 8; l++) s += sb[tid][l];
        g_b12r[tid] = s;
    }
}

// ------------------------- fused parnet: x -> constrained partial sums -----
// Phase 1: H tile (16 rows x 512) = elu(x@W0+b0) in SMEM.
// Phase 2: praw = H @ W12p + b12p -> constrain -> per-block partial sums.
__global__ void k_parnet(const float* __restrict__ X, const float* __restrict__ W0,
                         const float* __restrict__ b0, int T) {
    __shared__ float sH[TILE_R * HDIM];    // 32 KB
    __shared__ float sP[TILE_R][32];
    int tid = threadIdx.x;
    int row0 = blockIdx.x * TILE_R;

    for (int i = tid; i < TILE_R * HDIM; i += 256) {
        int r = i >> 9, j = i & 511;
        int gr = row0 + r;
        if (gr < T) {
            float s = b0[j];
            const float* xr = X + gr * 12;
            #pragma unroll
            for (int q = 0; q < 12; q++) s = fmaf(xr[q], W0[q * HDIM + j], s);
            sH[i] = s > 0.f ? s : expm1f(s);
        } else {
            sH[i] = 0.f;
        }
    }
    __syncthreads();

    for (int i = tid; i < TILE_R * 27; i += 256) {
        int r = i / 27, j = i - r * 27;
        float s = g_b12p[j];
        const float* hr = &sH[r * HDIM];
        const float* wc = &g_W12p[j];
        #pragma unroll 4
        for (int k = 0; k < HDIM; k++)
            s = fmaf(hr[k], wc[k * 27], s);
        sP[r][j] = (row0 + r < T) ? constrain(s, j) : 0.f;
    }
    __syncthreads();
    if (tid < 27) {
        float s = 0.f;
        #pragma unroll
        for (int r = 0; r < TILE_R; r++) s += sP[r][tid];
        g_P[blockIdx.x * 27 + tid] = s;
    }
}

// ------------------------- reduce partials -> pm, derived constants --------
__global__ void k_reduce(int nblk, int T) {
    int j = threadIdx.x >> 5, lane = threadIdx.x & 31;
    if (j < 27) {
        float s = 0.f;
        for (int b = lane; b < nblk; b += 32) s += g_P[b * 27 + j];
        #pragma unroll
        for (int o = 16; o; o >>= 1) s += __shfl_down_sync(0xffffffffu, s, o);
        if (lane == 0) g_pm[j] = s / (float)T * c_SCALES[j];
    }
    __syncthreads();
    if (threadIdx.x == 0) {
        float sd = g_pm[0], fc = g_pm[1], pwp = g_pm[2], tauD = g_pm[3], tau = g_pm[5];
        g_pm[27] = fc * sd;                              // fcap
        g_pm[28] = 1.f / sd;                             // inv soildepth
        g_pm[29] = 1.f / (fc - pwp);                     // inv (FC - PWP)
        g_pm[30] = 1.f / g_pm[10];                       // inv soilthres
        g_pm[31] = 1.f / g_pm[16];                       // inv ETsoilthres
        g_pm[32] = 1.f - 1.f / tau;                      // a (S recurrence)
        g_pm[33] = 1.f / tau;
        g_pm[34] = 1.f / g_pm[7];                        // inv Smax
        float invTauD = (tauD > 0.f) ? 1.f / tauD : 0.f;
        g_pm[35] = invTauD;
        g_pm[36] = 1.f - invTauD;                        // c1: theta=min(st0, st0*c1+c2)
        g_pm[37] = (g_pm[20] <= 1e-8f) ? 1.f : 0.f;      // small CWmax
        g_pm[38] = g_pm[19] / 0.75f;                     // I0/0.75
        g_pm[39] = g_pm[27] * invTauD;                   // c2
    }
}

// ------------------------- day precompute + S via truncated convolution ----
__global__ void k_day(const float* __restrict__ cin, int T) {
    __shared__ float sx[SK + 256 - 1 + 1];   // tair[base-(SK-1) .. base+255]
    __shared__ float pw[SK + 1];
    int base = blockIdx.x * 256;
    int tid = threadIdx.x;

    float tau = g_pm[5];
    float a = 1.f - 1.f / tau, invtau = 1.f / tau;
    float S0 = g_pm[6], invSmax = g_pm[34], Sinit = g_pm[26];

    for (int i = tid; i < SK + 255; i += 256) {
        int g = base - (SK - 1) + i;
        sx[i] = (g >= 0 && g < T) ? cin[g * 7 + 1] : 0.f;
    }
    for (int j = tid; j <= SK; j += 256) pw[j] = __powf(a, (float)j);
    __syncthreads();

    int t = base + tid;
    if (t >= T) return;

    int Kt = min(t + 1, SK);
    int off = tid + (SK - 1);    // sx index of x_t
    float s0 = 0.f, s1 = 0.f, s2 = 0.f, s3 = 0.f;
    int j = 0;
    for (; j + 4 <= Kt; j += 4) {
        s0 = fmaf(pw[j + 0], sx[off - j - 0], s0);
        s1 = fmaf(pw[j + 1], sx[off - j - 1], s1);
        s2 = fmaf(pw[j + 2], sx[off - j - 2], s2);
        s3 = fmaf(pw[j + 3], sx[off - j - 3], s3);
    }
    for (; j < Kt; j++) s0 = fmaf(pw[j], sx[off - j], s0);
    float S = ((s0 + s1) + (s2 + s3)) * invtau;
    if (t < SK) S = fmaf(pw[t + 1], Sinit, S);
    float fS = fminf(fmaxf(S - S0, 0.f) * invSmax, 1.f);

    float beta = g_pm[4], kappa = g_pm[8], gamma = g_pm[9];
    float bCO2 = g_pm[11], xCO2 = g_pm[12];
    float ETbeta = g_pm[13], ETkappa = g_pm[14], ETchi = g_pm[15];
    float MeltCoef = g_pm[18], CWmax = g_pm[20], ST = g_pm[21], T0p = g_pm[22];
    float Icoef = g_pm[38];

    float precip = cin[t * 7 + 0], tair = cin[t * 7 + 1], par = cin[t * 7 + 2];
    float vpd = cin[t * 7 + 3], fapar = cin[t * 7 + 4], co2 = cin[t * 7 + 6];

    float fD = fminf(__expf(kappa * vpd), 1.f);
    float fL = __fdividef(1.f, fmaf(gamma, par, 1.f));
    float G = beta * par * fapar * fS * fL;
    float lc = __logf(co2 * (1.f / 380.f));
    float GM = G * fmaf(bCO2, lc, 1.f);
    float fCO2et = fmaf(xCO2, lc, 1.f);
    float TRG = vpd * ETbeta * G * __powf(vpd, -ETkappa) * fCO2et;
    float EV = ETchi * (1.f - fapar) * par;
    float I = (tair > ST) ? precip * fapar * Icoef : 0.f;
    float R = precip - I;
    float cap = CWmax * fapar;
    float meltpot = (tair >= T0p) ? MeltCoef * (tair - T0p) : 0.f;

    g_dayA[t] = make_float4(GM, TRG, fD, EV);
    g_dayB[t] = make_float4(I, R, cap, meltpot);
    g_dayC[t] = (tair < ST) ? 1.f : 0.f;
}

// ------------------------- block-parallel decoupled water scan -------------
__global__ void k_scanP(const float* __restrict__ sw, float* __restrict__ pp, int T) {
    if (threadIdx.x != 0) return;
    int start = blockIdx.x * SEG_L;
    if (start >= T) return;
    int end = min(start + SEG_L, T);
    int wstart = max(start - WARM, 0);

    float PWP = g_pm[2], soilthres = g_pm[10], ETst = g_pm[16], ETnu = g_pm[17];
    float invSD = g_pm[28], invRange = g_pm[29], invST = g_pm[30], invETst = g_pm[31];
    float c1 = g_pm[36], c2 = g_pm[39];
    bool smallcw = g_pm[37] > 0.5f;
    float a1 = invSD * invRange, b1 = -PWP * invRange;   // REW = theta*a1 + b1

    float theta = g_pm[23], canw = g_pm[24], snow = g_pm[25];
    float sw0 = sw[0], invsw1 = 1.f / sw[1];

    auto step = [&](const float4 da, const float4 db, float cold,
                    float& gpp, float& et) {
        float REW = fmaf(theta, a1, b1);
        float fWmid = REW * invST;
        float pwin = fmaxf(fminf(fWmid, 1.f), 1e-12f);
        float pw = __powf(pwin, ETnu);
        float fW = (REW < soilthres) ? ((REW > 0.01f) ? fWmid : 0.f) : 1.f;
        float fE = fminf(da.z, fW);
        gpp = da.x * fE;
        float transp = da.y * fE * pw;

        float fwm2 = REW * invETst;
        float fWet = (REW < ETst) ? ((REW > 0.01f) ? fwm2 : 0.f) : 1.f;

        float I = db.x, R = db.y, cap = db.z;
        bool over = (I + canw) > cap;
        float tf = smallcw ? (R + I) : (over ? (R + I + canw - cap) : R);
        float canw1 = smallcw ? canw : (over ? cap : canw + I);
        if (canw1 > 1e-8f) fWet = 1.f;
        float evap = da.w * fWet;

        float newsnow = cold * tf;
        tf = tf - newsnow;
        float snn = snow + newsnow;
        float melt = fminf(db.w, snn);
        float snow1 = snn - melt;

        et = transp + evap;
        float etsoil = fmaxf(et - (canw1 + snow1), 0.f);
        float st0 = fmaxf(theta + tf + melt - etsoil, 1e-4f);
        theta = fminf(st0, fmaf(st0, c1, c2));

        canw = fmaxf(canw1 - et, 0.f);
        float rem = fmaxf(et - canw1, 0.f);
        snow = fmaxf(snow1 - rem, 0.f);
    };

    int t = wstart;
    for (; t + 4 <= start; t += 4) {
        float4 a0 = g_dayA[t], a01 = g_dayA[t + 1], a2 = g_dayA[t + 2], a3 = g_dayA[t + 3];
        float4 b0 = g_dayB[t], b01 = g_dayB[t + 1], b2 = g_dayB[t + 2], b3 = g_dayB[t + 3];
        float4 cc = *reinterpret_cast<const float4*>(&g_dayC[t]);
        float g, e;
        step(a0, b0, cc.x, g, e);
        step(a01, b01, cc.y, g, e);
        step(a2, b2, cc.z, g, e);
        step(a3, b3, cc.w, g, e);
    }
    for (; t < start; t++) { float g, e; step(g_dayA[t], g_dayB[t], g_dayC[t], g, e); }
    for (; t + 4 <= end; t += 4) {
        float4 a0 = g_dayA[t], a01 = g_dayA[t + 1], a2 = g_dayA[t + 2], a3 = g_dayA[t + 3];
        float4 b0 = g_dayB[t], b01 = g_dayB[t + 1], b2 = g_dayB[t + 2], b3 = g_dayB[t + 3];
        float4 cc = *reinterpret_cast<const float4*>(&g_dayC[t]);
        float g, e;
        step(a0, b0, cc.x, g, e);
        pp[3 * t + 0] = g; pp[3 * t + 1] = e; pp[3 * t + 2] = (theta - sw0) * invsw1;
        step(a01, b01, cc.y, g, e);
        pp[3 * t + 3] = g; pp[3 * t + 4] = e; pp[3 * t + 5] = (theta - sw0) * invsw1;
        step(a2, b2, cc.z, g, e);
        pp[3 * t + 6] = g; pp[3 * t + 7] = e; pp[3 * t + 8] = (theta - sw0) * invsw1;
        step(a3, b3, cc.w, g, e);
        pp[3 * t + 9] = g; pp[3 * t + 10] = e; pp[3 * t + 11] = (theta - sw0) * invsw1;
    }
    for (; t < end; t++) {
        float g, e;
        step(g_dayA[t], g_dayB[t], g_dayC[t], g, e);
        pp[3 * t + 0] = g; pp[3 * t + 1] = e; pp[3 * t + 2] = (theta - sw0) * invsw1;
    }
}

// ------------------------- fused resnet: pp -> y_hat -----------------------
// Warp-per-row: h = elu(pp@rW0+rb0) sliced across lanes, folded 512->2 dot.
__global__ void k_resnet(const float* __restrict__ pp, const float* __restrict__ rW0,
                         const float* __restrict__ rb0, float* __restrict__ yhat, int T) {
    __shared__ float srW0[3 * HDIM];   // [i][k]
    __shared__ float srb0[HDIM];
    __shared__ float srW12[2 * HDIM];  // transposed: [j][k]
    int tid = threadIdx.x;
    for (int i = tid; i < 3 * HDIM; i += 256) srW0[i] = rW0[i];
    for (int i = tid; i < HDIM; i += 256) srb0[i] = rb0[i];
    for (int i = tid; i < 2 * HDIM; i += 256) {
        int j = i >> 9, k = i & 511;
        srW12[i] = g_W12r[k * 2 + j];
    }
    __syncthreads();
    float bb0 = g_b12r[0], bb1 = g_b12r[1];

    int warp = tid >> 5, lane = tid & 31;
    for (int row = blockIdx.x * 8 + warp; row < T; row += gridDim.x * 8) {
        float x0 = pp[row * 3], x1 = pp[row * 3 + 1], x2 = pp[row * 3 + 2];
        float a0 = 0.f, a1 = 0.f;
        #pragma unroll
        for (int kk = 0; kk < 16; kk++) {
            int k = lane + kk * 32;
            float h = srb0[k];
            h = fmaf(x0, srW0[k], h);
            h = fmaf(x1, srW0[HDIM + k], h);
            h = fmaf(x2, srW0[2 * HDIM + k], h);
            h = h > 0.f ? h : expm1f(h);
            a0 = fmaf(h, srW12[k], a0);
            a1 = fmaf(h, srW12[HDIM + k], a1);
        }
        #pragma unroll
        for (int o = 16; o; o >>= 1) {
            a0 += __shfl_down_sync(0xffffffffu, a0, o);
            a1 += __shfl_down_sync(0xffffffffu, a1, o);
        }
        if (lane == 0) {
            yhat[row * 2 + 0] = a0 + bb0;
            yhat[row * 2 + 1] = a1 + bb1;
        }
    }
}

// ------------------------- launcher ----------------------------------------
extern "C" void kernel_launch(void* const* d_in, const int* in_sizes, int n_in,
                              void* d_out, int out_size) {
    const float* x   = (const float*)d_in[0];
    const float* cin = (const float*)d_in[1];
    const float* sw  = (const float*)d_in[2];
    // d_in[3] = tp (unused)
    const float* pW0 = (const float*)d_in[4];
    const float* pb0 = (const float*)d_in[5];
    const float* pW1 = (const float*)d_in[6];
    const float* pb1 = (const float*)d_in[7];
    const float* pW2 = (const float*)d_in[8];
    const float* pb2 = (const float*)d_in[9];
    const float* rW0 = (const float*)d_in[10];
    const float* rb0 = (const float*)d_in[11];
    const float* rW1 = (const float*)d_in[12];
    const float* rb1 = (const float*)d_in[13];
    const float* rW2 = (const float*)d_in[14];
    const float* rb2 = (const float*)d_in[15];

    int T = in_sizes[0] / 12;
    float* yhat = (float*)d_out;           // [T, 2]
    float* pp = yhat + 2 * T;              // [T, 3]

    int nblk = (T + TILE_R - 1) / TILE_R;
    int nseg = (T + SEG_L - 1) / SEG_L;

    // fold both linear-linear compositions (independent of data path)
    k_fold<<<32, 256>>>(pW1, pb1, pW2, pb2);
    k_rfold<<<32, 256>>>(rW1, rb1, rW2, rb2);

    // parnet (fused): x -> constrained partial sums -> pm
    k_parnet<<<nblk, 256>>>(x, pW0, pb0, T);
    k_reduce<<<1, 27 * 32>>>(nblk, T);

    // PRELES
    k_day<<<(T + 255) / 256, 256>>>(cin, T);
    k_scanP<<<nseg, 32>>>(sw, pp, T);

    // resnet (fused): pp -> y_hat
    k_resnet<<<148, 256>>>(pp, rW0, rb0, yhat, T);
}

// round 11
// speedup vs baseline: 3.2923x; 1.1739x over previous
#include <cuda_runtime.h>
#include <math.h>

#define HDIM 512
#define TILE_R 16
#define SEG_L 256          // output days per scan block
#define WARM 512           // warmup days (contraction burn-in)
#define SK 512             // S-convolution taps

// ------------------------- scratch (static device globals; no allocs) ------
__device__ float  g_P[27 * 4096];       // transposed partial sums: [j][block]
__device__ float  g_pm[64];             // 27 physical params + derived constants
__device__ float  g_W12p[HDIM * 32];    // folded parnet W1@W2, padded to 32 cols
__device__ float  g_b12p[32];           // folded parnet bias
__device__ float  g_W12r[HDIM * 2];     // folded resnet rW1@rW2
__device__ float  g_b12r[4];            // folded resnet bias
__device__ float4 g_dayA[50176];        // {GM, TRG, fD, EV}
__device__ float4 g_dayB[50176];        // {I, R, cap, meltpot}
__device__ __align__(16) float g_dayC[50176];  // cold flag

__constant__ float c_SCALES[27] = {400,1,1,1,1,12,10,10,1,1,1,1,1,10,1,1,1,5,1,1,4,1,1,180,1,1,10};

// ------------------------- parameter constraint ----------------------------
__device__ __forceinline__ float clampf(float v, float lo, float hi) {
    return fminf(fmaxf(v, lo), hi);
}
__device__ __forceinline__ float constrain(float v, int j) {
    switch (j) {
        case 0:  return clampf(v, 0.f, 2.f);
        case 1: case 2: case 20: case 21: case 23: case 24: case 25: case 26:
                 return fmaxf(v, 0.f);
        case 4:  return clampf(v, 0.f, 2.5f);
        case 5:  return clampf(v, 0.01f, 3.f);
        case 6:  return clampf(v, -0.2f, 2.1f);
        case 7:  return clampf(v, 0.23f, 3.0f);
        case 8:  return clampf(v, -1.f, 0.f);
        case 9:  return clampf(v, 0.f, 0.7f);
        case 10: case 16: return 1.f / (1.f + expf(-v));
        case 13: return clampf(v, 0.f, 1.0f);
        case 14: return clampf(v, 0.f, 1.2f);
        case 15: return clampf(v, 0.f, 2.5f);
        case 17: return clampf(v, 0.f, 1.f);
        case 19: return clampf(v, 0.f, 1.f / 0.75f);
        default: return v;   // 3, 11, 12, 18, 22
    }
}

// ------------------------- fold parnet W1@W2 (padded), b1@W2+b2 ------------
__global__ void k_fold(const float* __restrict__ W1, const float* __restrict__ b1,
                       const float* __restrict__ W2, const float* __restrict__ b2) {
    __shared__ float sW1[16 * HDIM];       // 32 KB
    __shared__ float sb[27][8];
    int tid = threadIdx.x;
    int k0 = blockIdx.x * 16;
    for (int i = tid; i < 16 * HDIM; i += 256)
        sW1[i] = W1[(k0 + (i >> 9)) * HDIM + (i & 511)];
    if (blockIdx.x == 0) {
        for (int i = tid; i < 27 * 8; i += 256) {
            int j = i >> 3, l = i & 7;
            float s = 0.f;
            for (int k = l * 64; k < l * 64 + 64; k++)
                s = fmaf(b1[k], W2[k * 27 + j], s);
            sb[j][l] = s;
        }
    }
    __syncthreads();
    for (int i = tid; i < 16 * 32; i += 256) {
        int kr = i >> 5, j = i & 31;
        float s = 0.f;
        if (j < 27) {
            const float* w1r = &sW1[kr * HDIM];
            #pragma unroll 4
            for (int m = 0; m < HDIM; m++)
                s = fmaf(w1r[m], W2[m * 27 + j], s);
        }
        g_W12p[(k0 + kr) * 32 + j] = s;
    }
    if (blockIdx.x == 0 && tid < 27) {
        float s = b2[tid];
        #pragma unroll
        for (int l = 0; l < 8; l++) s += sb[tid][l];
        g_b12p[tid] = s;
    }
}

// ------------------------- fold resnet rW1@rW2, rb1@rW2+rb2 ----------------
__global__ void k_rfold(const float* __restrict__ W1, const float* __restrict__ b1,
                        const float* __restrict__ W2, const float* __restrict__ b2) {
    __shared__ float sW1[16 * HDIM];
    __shared__ float sb[2][8];
    int tid = threadIdx.x;
    int k0 = blockIdx.x * 16;
    for (int i = tid; i < 16 * HDIM; i += 256)
        sW1[i] = W1[(k0 + (i >> 9)) * HDIM + (i & 511)];
    if (blockIdx.x == 0) {
        for (int i = tid; i < 2 * 8; i += 256) {
            int j = i >> 3, l = i & 7;
            float s = 0.f;
            for (int k = l * 64; k < l * 64 + 64; k++)
                s = fmaf(b1[k], W2[k * 2 + j], s);
            sb[j][l] = s;
        }
    }
    __syncthreads();
    for (int i = tid; i < 16 * 2; i += 256) {
        int kr = i >> 1, j = i & 1;
        float s = 0.f;
        const float* w1r = &sW1[kr * HDIM];
        #pragma unroll 4
        for (int m = 0; m < HDIM; m++)
            s = fmaf(w1r[m], W2[m * 2 + j], s);
        g_W12r[(k0 + kr) * 2 + j] = s;
    }
    if (blockIdx.x == 0 && tid < 2) {
        float s = b2[tid];
        #pragma unroll
        for (int l = 0; l < 8; l++) s += sb[tid][l];
        g_b12r[tid] = s;
    }
}

// ------------------------- fused parnet: x -> constrained partial sums -----
// Phase 1: H tile (16 x 512) = elu(x@W0+b0) in SMEM.
// Phase 2: warp w owns k-chunk [w*64,w*64+64); lane = output col j (coalesced
//          W12p loads, one pass over W12p per block); 16 row-accumulators.
// Combine: warp partials through SMEM scratch (fixed order), constrain, sum.
__global__ void k_parnet(const float* __restrict__ X, const float* __restrict__ W0,
                         const float* __restrict__ b0, int T) {
    __shared__ float sH[TILE_R * HDIM];    // 32 KB; reused as partial scratch
    __shared__ float sP[TILE_R][28];
    int tid = threadIdx.x;
    int warp = tid >> 5, lane = tid & 31;
    int row0 = blockIdx.x * TILE_R;

    for (int i = tid; i < TILE_R * HDIM; i += 256) {
        int r = i >> 9, j = i & 511;
        int gr = row0 + r;
        if (gr < T) {
            float s = b0[j];
            const float* xr = X + gr * 12;
            #pragma unroll
            for (int q = 0; q < 12; q++) s = fmaf(xr[q], W0[q * HDIM + j], s);
            sH[i] = s > 0.f ? s : expm1f(s);
        } else {
            sH[i] = 0.f;
        }
    }
    __syncthreads();

    float acc[TILE_R];
    #pragma unroll
    for (int r = 0; r < TILE_R; r++) acc[r] = 0.f;
    int kbase = warp * 64;
    #pragma unroll 4
    for (int kk = 0; kk < 64; kk += 2) {
        int k = kbase + kk;
        float w0 = g_W12p[k * 32 + lane];
        float w1 = g_W12p[(k + 1) * 32 + lane];
        #pragma unroll
        for (int r = 0; r < TILE_R; r++) {
            float2 h = *reinterpret_cast<const float2*>(&sH[r * HDIM + k]);
            acc[r] = fmaf(h.x, w0, acc[r]);
            acc[r] = fmaf(h.y, w1, acc[r]);
        }
    }
    __syncthreads();   // done reading sH
    #pragma unroll
    for (int r = 0; r < TILE_R; r++)
        sH[(warp * TILE_R + r) * 32 + lane] = acc[r];
    __syncthreads();

    for (int i = tid; i < TILE_R * 27; i += 256) {
        int r = i / 27, j = i - r * 27;
        float s = g_b12p[j];
        #pragma unroll
        for (int w = 0; w < 8; w++) s += sH[(w * TILE_R + r) * 32 + j];
        sP[r][j] = (row0 + r < T) ? constrain(s, j) : 0.f;
    }
    __syncthreads();
    if (tid < 27) {
        float s = 0.f;
        #pragma unroll
        for (int r = 0; r < TILE_R; r++) s += sP[r][tid];
        g_P[tid * 4096 + blockIdx.x] = s;   // transposed: coalesced reduce reads
    }
}

// ------------------------- reduce partials -> pm, derived constants --------
__global__ void k_reduce(int nblk, int T) {
    int j = threadIdx.x >> 5, lane = threadIdx.x & 31;
    if (j < 27) {
        float s = 0.f;
        for (int b = lane; b < nblk; b += 32) s += g_P[j * 4096 + b];
        #pragma unroll
        for (int o = 16; o; o >>= 1) s += __shfl_down_sync(0xffffffffu, s, o);
        if (lane == 0) g_pm[j] = s / (float)T * c_SCALES[j];
    }
    __syncthreads();
    if (threadIdx.x == 0) {
        float sd = g_pm[0], fc = g_pm[1], pwp = g_pm[2], tauD = g_pm[3], tau = g_pm[5];
        g_pm[27] = fc * sd;                              // fcap
        g_pm[28] = 1.f / sd;                             // inv soildepth
        g_pm[29] = 1.f / (fc - pwp);                     // inv (FC - PWP)
        g_pm[30] = 1.f / g_pm[10];                       // inv soilthres
        g_pm[31] = 1.f / g_pm[16];                       // inv ETsoilthres
        g_pm[32] = 1.f - 1.f / tau;                      // a (S recurrence)
        g_pm[33] = 1.f / tau;
        g_pm[34] = 1.f / g_pm[7];                        // inv Smax
        float invTauD = (tauD > 0.f) ? 1.f / tauD : 0.f;
        g_pm[35] = invTauD;
        g_pm[36] = 1.f - invTauD;                        // c1: theta=min(st0, st0*c1+c2)
        g_pm[37] = (g_pm[20] <= 1e-8f) ? 1.f : 0.f;      // small CWmax
        g_pm[38] = g_pm[19] / 0.75f;                     // I0/0.75
        g_pm[39] = g_pm[27] * invTauD;                   // c2
    }
}

// ------------------------- day precompute + S via truncated convolution ----
__global__ void k_day(const float* __restrict__ cin, int T) {
    __shared__ float sx[SK + 256 - 1 + 1];   // tair[base-(SK-1) .. base+255]
    __shared__ float pw[SK + 1];
    int base = blockIdx.x * 256;
    int tid = threadIdx.x;

    float tau = g_pm[5];
    float a = 1.f - 1.f / tau, invtau = 1.f / tau;
    float S0 = g_pm[6], invSmax = g_pm[34], Sinit = g_pm[26];

    for (int i = tid; i < SK + 255; i += 256) {
        int g = base - (SK - 1) + i;
        sx[i] = (g >= 0 && g < T) ? cin[g * 7 + 1] : 0.f;
    }
    for (int j = tid; j <= SK; j += 256) pw[j] = __powf(a, (float)j);
    __syncthreads();

    int t = base + tid;
    if (t >= T) return;

    int Kt = min(t + 1, SK);
    int off = tid + (SK - 1);    // sx index of x_t
    float s0 = 0.f, s1 = 0.f, s2 = 0.f, s3 = 0.f;
    int j = 0;
    for (; j + 4 <= Kt; j += 4) {
        s0 = fmaf(pw[j + 0], sx[off - j - 0], s0);
        s1 = fmaf(pw[j + 1], sx[off - j - 1], s1);
        s2 = fmaf(pw[j + 2], sx[off - j - 2], s2);
        s3 = fmaf(pw[j + 3], sx[off - j - 3], s3);
    }
    for (; j < Kt; j++) s0 = fmaf(pw[j], sx[off - j], s0);
    float S = ((s0 + s1) + (s2 + s3)) * invtau;
    if (t < SK) S = fmaf(pw[t + 1], Sinit, S);
    float fS = fminf(fmaxf(S - S0, 0.f) * invSmax, 1.f);

    float beta = g_pm[4], kappa = g_pm[8], gamma = g_pm[9];
    float bCO2 = g_pm[11], xCO2 = g_pm[12];
    float ETbeta = g_pm[13], ETkappa = g_pm[14], ETchi = g_pm[15];
    float MeltCoef = g_pm[18], CWmax = g_pm[20], ST = g_pm[21], T0p = g_pm[22];
    float Icoef = g_pm[38];

    float precip = cin[t * 7 + 0], tair = cin[t * 7 + 1], par = cin[t * 7 + 2];
    float vpd = cin[t * 7 + 3], fapar = cin[t * 7 + 4], co2 = cin[t * 7 + 6];

    float fD = fminf(__expf(kappa * vpd), 1.f);
    float fL = __fdividef(1.f, fmaf(gamma, par, 1.f));
    float G = beta * par * fapar * fS * fL;
    float lc = __logf(co2 * (1.f / 380.f));
    float GM = G * fmaf(bCO2, lc, 1.f);
    float fCO2et = fmaf(xCO2, lc, 1.f);
    float TRG = vpd * ETbeta * G * __powf(vpd, -ETkappa) * fCO2et;
    float EV = ETchi * (1.f - fapar) * par;
    float I = (tair > ST) ? precip * fapar * Icoef : 0.f;
    float R = precip - I;
    float cap = CWmax * fapar;
    float meltpot = (tair >= T0p) ? MeltCoef * (tair - T0p) : 0.f;

    g_dayA[t] = make_float4(GM, TRG, fD, EV);
    g_dayB[t] = make_float4(I, R, cap, meltpot);
    g_dayC[t] = (tair < ST) ? 1.f : 0.f;
}

// ------------------------- block-parallel decoupled water scan -------------
// Software-pipelined: next 4-day group prefetched into registers while the
// current group's recurrence runs, hiding L2 latency behind the compute chain.
__global__ void k_scanP(const float* __restrict__ sw, float* __restrict__ pp, int T) {
    if (threadIdx.x != 0) return;
    int start = blockIdx.x * SEG_L;
    if (start >= T) return;
    int end = min(start + SEG_L, T);
    int wstart = max(start - WARM, 0);

    float PWP = g_pm[2], soilthres = g_pm[10], ETst = g_pm[16], ETnu = g_pm[17];
    float invSD = g_pm[28], invRange = g_pm[29], invST = g_pm[30], invETst = g_pm[31];
    float c1 = g_pm[36], c2 = g_pm[39];
    bool smallcw = g_pm[37] > 0.5f;
    float a1 = invSD * invRange, b1 = -PWP * invRange;   // REW = theta*a1 + b1

    float theta = g_pm[23], canw = g_pm[24], snow = g_pm[25];
    float sw0 = sw[0], invsw1 = 1.f / sw[1];

    auto step = [&](const float4 da, const float4 db, float cold,
                    float& gpp, float& et) {
        float REW = fmaf(theta, a1, b1);
        float fWmid = REW * invST;
        float pwin = fmaxf(fminf(fWmid, 1.f), 1e-12f);
        float pw = __powf(pwin, ETnu);
        float fW = (REW < soilthres) ? ((REW > 0.01f) ? fWmid : 0.f) : 1.f;
        float fE = fminf(da.z, fW);
        gpp = da.x * fE;
        float transp = da.y * fE * pw;

        float fwm2 = REW * invETst;
        float fWet = (REW < ETst) ? ((REW > 0.01f) ? fwm2 : 0.f) : 1.f;

        float I = db.x, R = db.y, cap = db.z;
        bool over = (I + canw) > cap;
        float tf = smallcw ? (R + I) : (over ? (R + I + canw - cap) : R);
        float canw1 = smallcw ? canw : (over ? cap : canw + I);
        if (canw1 > 1e-8f) fWet = 1.f;
        float evap = da.w * fWet;

        float newsnow = cold * tf;
        tf = tf - newsnow;
        float snn = snow + newsnow;
        float melt = fminf(db.w, snn);
        float snow1 = snn - melt;

        et = transp + evap;
        float etsoil = fmaxf(et - (canw1 + snow1), 0.f);
        float st0 = fmaxf(theta + tf + melt - etsoil, 1e-4f);
        theta = fminf(st0, fmaf(st0, c1, c2));

        canw = fmaxf(canw1 - et, 0.f);
        float rem = fmaxf(et - canw1, 0.f);
        snow = fmaxf(snow1 - rem, 0.f);
    };

    float4 A0, A1, A2, A3, B0, B1, B2, B3, C;
    int t = wstart;
    bool piped = (t + 4 <= end);
    if (piped) {
        A0 = g_dayA[t]; A1 = g_dayA[t + 1]; A2 = g_dayA[t + 2]; A3 = g_dayA[t + 3];
        B0 = g_dayB[t]; B1 = g_dayB[t + 1]; B2 = g_dayB[t + 2]; B3 = g_dayB[t + 3];
        C = *reinterpret_cast<const float4*>(&g_dayC[t]);
    }
    // warmup: [wstart, start)  (both multiples of 4)
    for (; t + 4 <= start; t += 4) {
        float4 nA0, nA1, nA2, nA3, nB0, nB1, nB2, nB3, nC;
        int tn = t + 4;
        if (tn + 4 <= end) {
            nA0 = g_dayA[tn]; nA1 = g_dayA[tn + 1]; nA2 = g_dayA[tn + 2]; nA3 = g_dayA[tn + 3];
            nB0 = g_dayB[tn]; nB1 = g_dayB[tn + 1]; nB2 = g_dayB[tn + 2]; nB3 = g_dayB[tn + 3];
            nC = *reinterpret_cast<const float4*>(&g_dayC[tn]);
        }
        float g, e;
        step(A0, B0, C.x, g, e);
        step(A1, B1, C.y, g, e);
        step(A2, B2, C.z, g, e);
        step(A3, B3, C.w, g, e);
        A0 = nA0; A1 = nA1; A2 = nA2; A3 = nA3;
        B0 = nB0; B1 = nB1; B2 = nB2; B3 = nB3; C = nC;
    }
    // output: [start, end)
    for (; t + 4 <= end; t += 4) {
        float4 nA0, nA1, nA2, nA3, nB0, nB1, nB2, nB3, nC;
        int tn = t + 4;
        if (tn + 4 <= end) {
            nA0 = g_dayA[tn]; nA1 = g_dayA[tn + 1]; nA2 = g_dayA[tn + 2]; nA3 = g_dayA[tn + 3];
            nB0 = g_dayB[tn]; nB1 = g_dayB[tn + 1]; nB2 = g_dayB[tn + 2]; nB3 = g_dayB[tn + 3];
            nC = *reinterpret_cast<const float4*>(&g_dayC[tn]);
        }
        float g, e;
        step(A0, B0, C.x, g, e);
        pp[3 * t + 0] = g; pp[3 * t + 1] = e; pp[3 * t + 2] = (theta - sw0) * invsw1;
        step(A1, B1, C.y, g, e);
        pp[3 * t + 3] = g; pp[3 * t + 4] = e; pp[3 * t + 5] = (theta - sw0) * invsw1;
        step(A2, B2, C.z, g, e);
        pp[3 * t + 6] = g; pp[3 * t + 7] = e; pp[3 * t + 8] = (theta - sw0) * invsw1;
        step(A3, B3, C.w, g, e);
        pp[3 * t + 9] = g; pp[3 * t + 10] = e; pp[3 * t + 11] = (theta - sw0) * invsw1;
        A0 = nA0; A1 = nA1; A2 = nA2; A3 = nA3;
        B0 = nB0; B1 = nB1; B2 = nB2; B3 = nB3; C = nC;
    }
    for (; t < end; t++) {   // scalar tail (T not multiple of 4)
        float g, e;
        step(g_dayA[t], g_dayB[t], g_dayC[t], g, e);
        pp[3 * t + 0] = g; pp[3 * t + 1] = e; pp[3 * t + 2] = (theta - sw0) * invsw1;
    }
}

// ------------------------- fused resnet: pp -> y_hat -----------------------
__global__ void k_resnet(const float* __restrict__ pp, const float* __restrict__ rW0,
                         const float* __restrict__ rb0, float* __restrict__ yhat, int T) {
    __shared__ float srW0[3 * HDIM];   // [i][k]
    __shared__ float srb0[HDIM];
    __shared__ float srW12[2 * HDIM];  // transposed: [j][k]
    int tid = threadIdx.x;
    for (int i = tid; i < 3 * HDIM; i += 256) srW0[i] = rW0[i];
    for (int i = tid; i < HDIM; i += 256) srb0[i] = rb0[i];
    for (int i = tid; i < 2 * HDIM; i += 256) {
        int j = i >> 9, k = i & 511;
        srW12[i] = g_W12r[k * 2 + j];
    }
    __syncthreads();
    float bb0 = g_b12r[0], bb1 = g_b12r[1];

    int warp = tid >> 5, lane = tid & 31;
    for (int row = blockIdx.x * 8 + warp; row < T; row += gridDim.x * 8) {
        float x0 = pp[row * 3], x1 = pp[row * 3 + 1], x2 = pp[row * 3 + 2];
        float a0 = 0.f, a1 = 0.f;
        #pragma unroll
        for (int kk = 0; kk < 16; kk++) {
            int k = lane + kk * 32;
            float h = srb0[k];
            h = fmaf(x0, srW0[k], h);
            h = fmaf(x1, srW0[HDIM + k], h);
            h = fmaf(x2, srW0[2 * HDIM + k], h);
            h = h > 0.f ? h : expm1f(h);
            a0 = fmaf(h, srW12[k], a0);
            a1 = fmaf(h, srW12[HDIM + k], a1);
        }
        #pragma unroll
        for (int o = 16; o; o >>= 1) {
            a0 += __shfl_down_sync(0xffffffffu, a0, o);
            a1 += __shfl_down_sync(0xffffffffu, a1, o);
        }
        if (lane == 0) {
            yhat[row * 2 + 0] = a0 + bb0;
            yhat[row * 2 + 1] = a1 + bb1;
        }
    }
}

// ------------------------- launcher ----------------------------------------
extern "C" void kernel_launch(void* const* d_in, const int* in_sizes, int n_in,
                              void* d_out, int out_size) {
    const float* x   = (const float*)d_in[0];
    const float* cin = (const float*)d_in[1];
    const float* sw  = (const float*)d_in[2];
    // d_in[3] = tp (unused)
    const float* pW0 = (const float*)d_in[4];
    const float* pb0 = (const float*)d_in[5];
    const float* pW1 = (const float*)d_in[6];
    const float* pb1 = (const float*)d_in[7];
    const float* pW2 = (const float*)d_in[8];
    const float* pb2 = (const float*)d_in[9];
    const float* rW0 = (const float*)d_in[10];
    const float* rb0 = (const float*)d_in[11];
    const float* rW1 = (const float*)d_in[12];
    const float* rb1 = (const float*)d_in[13];
    const float* rW2 = (const float*)d_in[14];
    const float* rb2 = (const float*)d_in[15];

    int T = in_sizes[0] / 12;
    float* yhat = (float*)d_out;           // [T, 2]
    float* pp = yhat + 2 * T;              // [T, 3]

    int nblk = (T + TILE_R - 1) / TILE_R;
    int nseg = (T + SEG_L - 1) / SEG_L;

    // fold both linear-linear compositions (independent of data path)
    k_fold<<<32, 256>>>(pW1, pb1, pW2, pb2);
    k_rfold<<<32, 256>>>(rW1, rb1, rW2, rb2);

    // parnet (fused): x -> constrained partial sums -> pm
    k_parnet<<<nblk, 256>>>(x, pW0, pb0, T);
    k_reduce<<<1, 27 * 32>>>(nblk, T);

    // PRELES
    k_day<<<(T + 255) / 256, 256>>>(cin, T);
    k_scanP<<<nseg, 32>>>(sw, pp, T);

    // resnet (fused): pp -> y_hat
    k_resnet<<<148, 256>>>(pp, rW0, rb0, yhat, T);
}

// round 12
// speedup vs baseline: 6.5997x; 2.0046x over previous
#include <cuda_runtime.h>
#include <math.h>

#define HDIM 512
#define TILE_R 16
#define SEG_L 128          // output days per scan block
#define WARM 512           // warmup days (contraction burn-in)
#define SK 512             // S-convolution taps

// ------------------------- scratch (static device globals; no allocs) ------
__device__ float  g_P[27 * 4096];       // transposed partial sums: [j][block]
__device__ float  g_pm[64];             // 27 physical params + derived constants
__device__ float  g_W12p[HDIM * 32];    // folded parnet W1@W2, padded to 32 cols
__device__ float  g_b12p[32];           // folded parnet bias
__device__ float  g_W12r[HDIM * 2];     // folded resnet rW1@rW2
__device__ float  g_b12r[4];            // folded resnet bias
__device__ float4 g_dayA[50176];        // {GM, TRG, fD, EV}
__device__ float4 g_dayB[50176];        // {I, R, cap, meltpot}
__device__ __align__(16) float g_dayC[50176];  // cold flag

__constant__ float c_SCALES[27] = {400,1,1,1,1,12,10,10,1,1,1,1,1,10,1,1,1,5,1,1,4,1,1,180,1,1,10};

// ------------------------- parameter constraint ----------------------------
__device__ __forceinline__ float clampf(float v, float lo, float hi) {
    return fminf(fmaxf(v, lo), hi);
}
__device__ __forceinline__ float constrain(float v, int j) {
    switch (j) {
        case 0:  return clampf(v, 0.f, 2.f);
        case 1: case 2: case 20: case 21: case 23: case 24: case 25: case 26:
                 return fmaxf(v, 0.f);
        case 4:  return clampf(v, 0.f, 2.5f);
        case 5:  return clampf(v, 0.01f, 3.f);
        case 6:  return clampf(v, -0.2f, 2.1f);
        case 7:  return clampf(v, 0.23f, 3.0f);
        case 8:  return clampf(v, -1.f, 0.f);
        case 9:  return clampf(v, 0.f, 0.7f);
        case 10: case 16: return 1.f / (1.f + expf(-v));
        case 13: return clampf(v, 0.f, 1.0f);
        case 14: return clampf(v, 0.f, 1.2f);
        case 15: return clampf(v, 0.f, 2.5f);
        case 17: return clampf(v, 0.f, 1.f);
        case 19: return clampf(v, 0.f, 1.f / 0.75f);
        default: return v;   // 3, 11, 12, 18, 22
    }
}

// ------------------------- fold both W1@W2 compositions (one launch) -------
// Blocks [0,32): parnet fold -> g_W12p (padded 32 cols), g_b12p.
// Blocks [32,64): resnet fold -> g_W12r (2 cols), g_b12r.
__global__ void k_folds(const float* __restrict__ W1p, const float* __restrict__ b1p,
                        const float* __restrict__ W2p, const float* __restrict__ b2p,
                        const float* __restrict__ W1r, const float* __restrict__ b1r,
                        const float* __restrict__ W2r, const float* __restrict__ b2r) {
    __shared__ float sW1[16 * HDIM];       // 32 KB
    __shared__ float sb[32][8];
    int tid = threadIdx.x;
    bool isr = blockIdx.x >= 32;
    const float* W1 = isr ? W1r : W1p;
    const float* b1 = isr ? b1r : b1p;
    const float* W2 = isr ? W2r : W2p;
    const float* b2 = isr ? b2r : b2p;
    float* out  = isr ? g_W12r : g_W12p;
    float* bout = isr ? g_b12r : g_b12p;
    int NOUT = isr ? 2 : 27;
    int OP   = isr ? 2 : 32;       // output pitch
    int blk  = isr ? blockIdx.x - 32 : blockIdx.x;
    int k0 = blk * 16;

    for (int i = tid; i < 16 * HDIM; i += 256)
        sW1[i] = W1[(k0 + (i >> 9)) * HDIM + (i & 511)];
    if (blk == 0) {
        for (int i = tid; i < NOUT * 8; i += 256) {
            int j = i >> 3, l = i & 7;
            float s = 0.f;
            for (int k = l * 64; k < l * 64 + 64; k++)
                s = fmaf(b1[k], W2[k * NOUT + j], s);
            sb[j][l] = s;
        }
    }
    __syncthreads();
    for (int i = tid; i < 16 * OP; i += 256) {
        int kr = i / OP, j = i - kr * OP;
        float s = 0.f;
        if (j < NOUT) {
            const float* w1r = &sW1[kr * HDIM];
            #pragma unroll 4
            for (int m = 0; m < HDIM; m++)
                s = fmaf(w1r[m], W2[m * NOUT + j], s);
        }
        out[(k0 + kr) * OP + j] = s;
    }
    if (blk == 0 && tid < NOUT) {
        float s = b2[tid];
        #pragma unroll
        for (int l = 0; l < 8; l++) s += sb[tid][l];
        bout[tid] = s;
    }
}

// ------------------------- fused parnet: x -> constrained partial sums -----
// Phase 1: X tile staged in SMEM; W0 columns hoisted to registers; H tile
//          built with ~26 LDG/thread instead of ~768.
// Phase 2: warp w owns k-chunk [w*64,w*64+64); lane = output col j; float4
//          sH reads; 16 row-accumulators; one pass over W12p per block.
__global__ void __launch_bounds__(256)
k_parnet(const float* __restrict__ X, const float* __restrict__ W0,
         const float* __restrict__ b0, int T) {
    __shared__ float sH[TILE_R * HDIM];    // 32 KB; reused as partial scratch
    __shared__ float sX[TILE_R][12];
    __shared__ float sP[TILE_R][28];
    int tid = threadIdx.x;
    int warp = tid >> 5, lane = tid & 31;
    int row0 = blockIdx.x * TILE_R;

    if (tid < TILE_R * 12) {
        int r = tid / 12, q = tid - r * 12;
        int gr = row0 + r;
        sX[r][q] = (gr < T) ? X[gr * 12 + q] : 0.f;
    }
    __syncthreads();

    {
        float w0a[12], w0b[12];
        #pragma unroll
        for (int q = 0; q < 12; q++) {
            w0a[q] = W0[q * HDIM + tid];
            w0b[q] = W0[q * HDIM + tid + 256];
        }
        float b0a = b0[tid], b0b = b0[tid + 256];
        #pragma unroll
        for (int r = 0; r < TILE_R; r++) {
            float sa = b0a, sb2 = b0b;
            #pragma unroll
            for (int q = 0; q < 12; q++) {
                float xv = sX[r][q];
                sa  = fmaf(xv, w0a[q], sa);
                sb2 = fmaf(xv, w0b[q], sb2);
            }
            sH[r * HDIM + tid]       = sa  > 0.f ? sa  : expm1f(sa);
            sH[r * HDIM + tid + 256] = sb2 > 0.f ? sb2 : expm1f(sb2);
        }
    }
    __syncthreads();

    float acc[TILE_R];
    #pragma unroll
    for (int r = 0; r < TILE_R; r++) acc[r] = 0.f;
    int kbase = warp * 64;
    #pragma unroll
    for (int kk = 0; kk < 64; kk += 4) {
        int k = kbase + kk;
        float w0 = g_W12p[(k + 0) * 32 + lane];
        float w1 = g_W12p[(k + 1) * 32 + lane];
        float w2 = g_W12p[(k + 2) * 32 + lane];
        float w3 = g_W12p[(k + 3) * 32 + lane];
        #pragma unroll
        for (int r = 0; r < TILE_R; r++) {
            float4 h = *reinterpret_cast<const float4*>(&sH[r * HDIM + k]);
            acc[r] = fmaf(h.x, w0, acc[r]);
            acc[r] = fmaf(h.y, w1, acc[r]);
            acc[r] = fmaf(h.z, w2, acc[r]);
            acc[r] = fmaf(h.w, w3, acc[r]);
        }
    }
    __syncthreads();   // done reading sH
    #pragma unroll
    for (int r = 0; r < TILE_R; r++)
        sH[(warp * TILE_R + r) * 32 + lane] = acc[r];
    __syncthreads();

    for (int i = tid; i < TILE_R * 27; i += 256) {
        int r = i / 27, j = i - r * 27;
        float s = g_b12p[j];
        #pragma unroll
        for (int w = 0; w < 8; w++) s += sH[(w * TILE_R + r) * 32 + j];
        sP[r][j] = (row0 + r < T) ? constrain(s, j) : 0.f;
    }
    __syncthreads();
    if (tid < 27) {
        float s = 0.f;
        #pragma unroll
        for (int r = 0; r < TILE_R; r++) s += sP[r][tid];
        g_P[tid * 4096 + blockIdx.x] = s;   // transposed: coalesced reduce reads
    }
}

// ------------------------- reduce partials -> pm, derived constants --------
__global__ void k_reduce(int nblk, int T) {
    int j = threadIdx.x >> 5, lane = threadIdx.x & 31;
    if (j < 27) {
        float s0 = 0.f, s1 = 0.f, s2 = 0.f, s3 = 0.f;
        const float* row = &g_P[j * 4096];
        int b = lane;
        for (; b + 96 < nblk; b += 128) {
            s0 += row[b]; s1 += row[b + 32]; s2 += row[b + 64]; s3 += row[b + 96];
        }
        for (; b < nblk; b += 32) s0 += row[b];
        float s = (s0 + s1) + (s2 + s3);
        #pragma unroll
        for (int o = 16; o; o >>= 1) s += __shfl_down_sync(0xffffffffu, s, o);
        if (lane == 0) g_pm[j] = s / (float)T * c_SCALES[j];
    }
    __syncthreads();
    if (threadIdx.x == 0) {
        float sd = g_pm[0], fc = g_pm[1], pwp = g_pm[2], tauD = g_pm[3], tau = g_pm[5];
        g_pm[27] = fc * sd;                              // fcap
        g_pm[28] = 1.f / sd;                             // inv soildepth
        g_pm[29] = 1.f / (fc - pwp);                     // inv (FC - PWP)
        g_pm[30] = 1.f / g_pm[10];                       // inv soilthres
        g_pm[31] = 1.f / g_pm[16];                       // inv ETsoilthres
        g_pm[32] = 1.f - 1.f / tau;                      // a (S recurrence)
        g_pm[33] = 1.f / tau;
        g_pm[34] = 1.f / g_pm[7];                        // inv Smax
        float invTauD = (tauD > 0.f) ? 1.f / tauD : 0.f;
        g_pm[35] = invTauD;
        g_pm[36] = 1.f - invTauD;                        // c1: theta=min(st0, st0*c1+c2)
        g_pm[37] = (g_pm[20] <= 1e-8f) ? 1.f : 0.f;      // small CWmax
        g_pm[38] = g_pm[19] / 0.75f;                     // I0/0.75
        g_pm[39] = g_pm[27] * invTauD;                   // c2
    }
}

// ------------------------- day precompute + S via truncated convolution ----
__global__ void k_day(const float* __restrict__ cin, int T) {
    __shared__ float sx[SK + 256 - 1 + 1];   // tair[base-(SK-1) .. base+255]
    __shared__ float pw[SK + 1];
    int base = blockIdx.x * 256;
    int tid = threadIdx.x;

    float tau = g_pm[5];
    float a = 1.f - 1.f / tau, invtau = 1.f / tau;
    float S0 = g_pm[6], invSmax = g_pm[34], Sinit = g_pm[26];

    for (int i = tid; i < SK + 255; i += 256) {
        int g = base - (SK - 1) + i;
        sx[i] = (g >= 0 && g < T) ? cin[g * 7 + 1] : 0.f;
    }
    for (int j = tid; j <= SK; j += 256) pw[j] = __powf(a, (float)j);
    __syncthreads();

    int t = base + tid;
    if (t >= T) return;

    int Kt = min(t + 1, SK);
    int off = tid + (SK - 1);    // sx index of x_t
    float s0 = 0.f, s1 = 0.f, s2 = 0.f, s3 = 0.f;
    int j = 0;
    for (; j + 4 <= Kt; j += 4) {
        s0 = fmaf(pw[j + 0], sx[off - j - 0], s0);
        s1 = fmaf(pw[j + 1], sx[off - j - 1], s1);
        s2 = fmaf(pw[j + 2], sx[off - j - 2], s2);
        s3 = fmaf(pw[j + 3], sx[off - j - 3], s3);
    }
    for (; j < Kt; j++) s0 = fmaf(pw[j], sx[off - j], s0);
    float S = ((s0 + s1) + (s2 + s3)) * invtau;
    if (t < SK) S = fmaf(pw[t + 1], Sinit, S);
    float fS = fminf(fmaxf(S - S0, 0.f) * invSmax, 1.f);

    float beta = g_pm[4], kappa = g_pm[8], gamma = g_pm[9];
    float bCO2 = g_pm[11], xCO2 = g_pm[12];
    float ETbeta = g_pm[13], ETkappa = g_pm[14], ETchi = g_pm[15];
    float MeltCoef = g_pm[18], CWmax = g_pm[20], ST = g_pm[21], T0p = g_pm[22];
    float Icoef = g_pm[38];

    float precip = cin[t * 7 + 0], tair = cin[t * 7 + 1], par = cin[t * 7 + 2];
    float vpd = cin[t * 7 + 3], fapar = cin[t * 7 + 4], co2 = cin[t * 7 + 6];

    float fD = fminf(__expf(kappa * vpd), 1.f);
    float fL = __fdividef(1.f, fmaf(gamma, par, 1.f));
    float G = beta * par * fapar * fS * fL;
    float lc = __logf(co2 * (1.f / 380.f));
    float GM = G * fmaf(bCO2, lc, 1.f);
    float fCO2et = fmaf(xCO2, lc, 1.f);
    float TRG = vpd * ETbeta * G * __powf(vpd, -ETkappa) * fCO2et;
    float EV = ETchi * (1.f - fapar) * par;
    float I = (tair > ST) ? precip * fapar * Icoef : 0.f;
    float R = precip - I;
    float cap = CWmax * fapar;
    float meltpot = (tair >= T0p) ? MeltCoef * (tair - T0p) : 0.f;

    g_dayA[t] = make_float4(GM, TRG, fD, EV);
    g_dayB[t] = make_float4(I, R, cap, meltpot);
    g_dayC[t] = (tair < ST) ? 1.f : 0.f;
}

// ------------------------- block-parallel decoupled water scan -------------
// Software-pipelined: next 4-day group prefetched into registers while the
// current group's recurrence runs, hiding L2 latency behind the compute chain.
__global__ void k_scanP(const float* __restrict__ sw, float* __restrict__ pp, int T) {
    if (threadIdx.x != 0) return;
    int start = blockIdx.x * SEG_L;
    if (start >= T) return;
    int end = min(start + SEG_L, T);
    int wstart = max(start - WARM, 0);

    float PWP = g_pm[2], soilthres = g_pm[10], ETst = g_pm[16], ETnu = g_pm[17];
    float invSD = g_pm[28], invRange = g_pm[29], invST = g_pm[30], invETst = g_pm[31];
    float c1 = g_pm[36], c2 = g_pm[39];
    bool smallcw = g_pm[37] > 0.5f;
    float a1 = invSD * invRange, b1 = -PWP * invRange;   // REW = theta*a1 + b1

    float theta = g_pm[23], canw = g_pm[24], snow = g_pm[25];
    float sw0 = sw[0], invsw1 = 1.f / sw[1];

    auto step = [&](const float4 da, const float4 db, float cold,
                    float& gpp, float& et) {
        float REW = fmaf(theta, a1, b1);
        float fWmid = REW * invST;
        float pwin = fmaxf(fminf(fWmid, 1.f), 1e-12f);
        float pw = __powf(pwin, ETnu);
        float fW = (REW < soilthres) ? ((REW > 0.01f) ? fWmid : 0.f) : 1.f;
        float fE = fminf(da.z, fW);
        gpp = da.x * fE;
        float transp = da.y * fE * pw;

        float fwm2 = REW * invETst;
        float fWet = (REW < ETst) ? ((REW > 0.01f) ? fwm2 : 0.f) : 1.f;

        float I = db.x, R = db.y, cap = db.z;
        bool over = (I + canw) > cap;
        float tf = smallcw ? (R + I) : (over ? (R + I + canw - cap) : R);
        float canw1 = smallcw ? canw : (over ? cap : canw + I);
        if (canw1 > 1e-8f) fWet = 1.f;
        float evap = da.w * fWet;

        float newsnow = cold * tf;
        tf = tf - newsnow;
        float snn = snow + newsnow;
        float melt = fminf(db.w, snn);
        float snow1 = snn - melt;

        et = transp + evap;
        float etsoil = fmaxf(et - (canw1 + snow1), 0.f);
        float st0 = fmaxf(theta + tf + melt - etsoil, 1e-4f);
        theta = fminf(st0, fmaf(st0, c1, c2));

        canw = fmaxf(canw1 - et, 0.f);
        float rem = fmaxf(et - canw1, 0.f);
        snow = fmaxf(snow1 - rem, 0.f);
    };

    float4 A0, A1, A2, A3, B0, B1, B2, B3, C;
    int t = wstart;
    bool piped = (t + 4 <= end);
    if (piped) {
        A0 = g_dayA[t]; A1 = g_dayA[t + 1]; A2 = g_dayA[t + 2]; A3 = g_dayA[t + 3];
        B0 = g_dayB[t]; B1 = g_dayB[t + 1]; B2 = g_dayB[t + 2]; B3 = g_dayB[t + 3];
        C = *reinterpret_cast<const float4*>(&g_dayC[t]);
    }
    // warmup: [wstart, start)  (both multiples of 4)
    for (; t + 4 <= start; t += 4) {
        float4 nA0, nA1, nA2, nA3, nB0, nB1, nB2, nB3, nC;
        int tn = t + 4;
        if (tn + 4 <= end) {
            nA0 = g_dayA[tn]; nA1 = g_dayA[tn + 1]; nA2 = g_dayA[tn + 2]; nA3 = g_dayA[tn + 3];
            nB0 = g_dayB[tn]; nB1 = g_dayB[tn + 1]; nB2 = g_dayB[tn + 2]; nB3 = g_dayB[tn + 3];
            nC = *reinterpret_cast<const float4*>(&g_dayC[tn]);
        }
        float g, e;
        step(A0, B0, C.x, g, e);
        step(A1, B1, C.y, g, e);
        step(A2, B2, C.z, g, e);
        step(A3, B3, C.w, g, e);
        A0 = nA0; A1 = nA1; A2 = nA2; A3 = nA3;
        B0 = nB0; B1 = nB1; B2 = nB2; B3 = nB3; C = nC;
    }
    // output: [start, end)
    for (; t + 4 <= end; t += 4) {
        float4 nA0, nA1, nA2, nA3, nB0, nB1, nB2, nB3, nC;
        int tn = t + 4;
        if (tn + 4 <= end) {
            nA0 = g_dayA[tn]; nA1 = g_dayA[tn + 1]; nA2 = g_dayA[tn + 2]; nA3 = g_dayA[tn + 3];
            nB0 = g_dayB[tn]; nB1 = g_dayB[tn + 1]; nB2 = g_dayB[tn + 2]; nB3 = g_dayB[tn + 3];
            nC = *reinterpret_cast<const float4*>(&g_dayC[tn]);
        }
        float g, e;
        step(A0, B0, C.x, g, e);
        pp[3 * t + 0] = g; pp[3 * t + 1] = e; pp[3 * t + 2] = (theta - sw0) * invsw1;
        step(A1, B1, C.y, g, e);
        pp[3 * t + 3] = g; pp[3 * t + 4] = e; pp[3 * t + 5] = (theta - sw0) * invsw1;
        step(A2, B2, C.z, g, e);
        pp[3 * t + 6] = g; pp[3 * t + 7] = e; pp[3 * t + 8] = (theta - sw0) * invsw1;
        step(A3, B3, C.w, g, e);
        pp[3 * t + 9] = g; pp[3 * t + 10] = e; pp[3 * t + 11] = (theta - sw0) * invsw1;
        A0 = nA0; A1 = nA1; A2 = nA2; A3 = nA3;
        B0 = nB0; B1 = nB1; B2 = nB2; B3 = nB3; C = nC;
    }
    for (; t < end; t++) {   // scalar tail (T not multiple of 4)
        float g, e;
        step(g_dayA[t], g_dayB[t], g_dayC[t], g, e);
        pp[3 * t + 0] = g; pp[3 * t + 1] = e; pp[3 * t + 2] = (theta - sw0) * invsw1;
    }
}

// ------------------------- fused resnet: pp -> y_hat -----------------------
__global__ void k_resnet(const float* __restrict__ pp, const float* __restrict__ rW0,
                         const float* __restrict__ rb0, float* __restrict__ yhat, int T) {
    __shared__ float srW0[3 * HDIM];   // [i][k]
    __shared__ float srb0[HDIM];
    __shared__ float srW12[2 * HDIM];  // transposed: [j][k]
    int tid = threadIdx.x;
    for (int i = tid; i < 3 * HDIM; i += 256) srW0[i] = rW0[i];
    for (int i = tid; i < HDIM; i += 256) srb0[i] = rb0[i];
    for (int i = tid; i < 2 * HDIM; i += 256) {
        int j = i >> 9, k = i & 511;
        srW12[i] = g_W12r[k * 2 + j];
    }
    __syncthreads();
    float bb0 = g_b12r[0], bb1 = g_b12r[1];

    int warp = tid >> 5, lane = tid & 31;
    for (int row = blockIdx.x * 8 + warp; row < T; row += gridDim.x * 8) {
        float x0 = pp[row * 3], x1 = pp[row * 3 + 1], x2 = pp[row * 3 + 2];
        float a0 = 0.f, a1 = 0.f;
        #pragma unroll
        for (int kk = 0; kk < 16; kk++) {
            int k = lane + kk * 32;
            float h = srb0[k];
            h = fmaf(x0, srW0[k], h);
            h = fmaf(x1, srW0[HDIM + k], h);
            h = fmaf(x2, srW0[2 * HDIM + k], h);
            h = h > 0.f ? h : expm1f(h);
            a0 = fmaf(h, srW12[k], a0);
            a1 = fmaf(h, srW12[HDIM + k], a1);
        }
        #pragma unroll
        for (int o = 16; o; o >>= 1) {
            a0 += __shfl_down_sync(0xffffffffu, a0, o);
            a1 += __shfl_down_sync(0xffffffffu, a1, o);
        }
        if (lane == 0) {
            yhat[row * 2 + 0] = a0 + bb0;
            yhat[row * 2 + 1] = a1 + bb1;
        }
    }
}

// ------------------------- launcher ----------------------------------------
extern "C" void kernel_launch(void* const* d_in, const int* in_sizes, int n_in,
                              void* d_out, int out_size) {
    const float* x   = (const float*)d_in[0];
    const float* cin = (const float*)d_in[1];
    const float* sw  = (const float*)d_in[2];
    // d_in[3] = tp (unused)
    const float* pW0 = (const float*)d_in[4];
    const float* pb0 = (const float*)d_in[5];
    const float* pW1 = (const float*)d_in[6];
    const float* pb1 = (const float*)d_in[7];
    const float* pW2 = (const float*)d_in[8];
    const float* pb2 = (const float*)d_in[9];
    const float* rW0 = (const float*)d_in[10];
    const float* rb0 = (const float*)d_in[11];
    const float* rW1 = (const float*)d_in[12];
    const float* rb1 = (const float*)d_in[13];
    const float* rW2 = (const float*)d_in[14];
    const float* rb2 = (const float*)d_in[15];

    int T = in_sizes[0] / 12;
    float* yhat = (float*)d_out;           // [T, 2]
    float* pp = yhat + 2 * T;              // [T, 3]

    int nblk = (T + TILE_R - 1) / TILE_R;
    int nseg = (T + SEG_L - 1) / SEG_L;

    // fold both linear-linear compositions (one launch, independent halves)
    k_folds<<<64, 256>>>(pW1, pb1, pW2, pb2, rW1, rb1, rW2, rb2);

    // parnet (fused): x -> constrained partial sums -> pm
    k_parnet<<<nblk, 256>>>(x, pW0, pb0, T);
    k_reduce<<<1, 27 * 32>>>(nblk, T);

    // PRELES
    k_day<<<(T + 255) / 256, 256>>>(cin, T);
    k_scanP<<<nseg, 32>>>(sw, pp, T);

    // resnet (fused): pp -> y_hat
    k_resnet<<<148, 256>>>(pp, rW0, rb0, yhat, T);
}